// round 1
// baseline (speedup 1.0000x reference)
#include <cuda_runtime.h>
#include <math.h>

#define NN   100000
#define EE   400000
#define GG   2048
#define HH   256
#define H2   512
#define LLAY 5
#define AFEA 9
#define BFEA 3
#define AVOC 128
#define BVOC 16
#define BN_EPS 1e-5f

// Output layout (flattened float32), total 1,156,769 elements:
#define O_HS   0                      // head(sub)   [G,2]
#define O_HT   (2*GG)                 // head(triv)  [G,2]
#define O_SUB  (4*GG)                 // sub         [G,H]
#define O_GE   (4*GG + GG*HH)         // graph_emb   [G,H]
#define O_MASK (4*GG + 2*GG*HH)       // active_mask [N]
#define O_PEN  (4*GG + 2*GG*HH + NN)  // con_penalty scalar

// ---------------- scratch (device globals; no allocs allowed) ----------------
__device__ float g_h[(size_t)NN * HH];
__device__ float g_agg[(size_t)NN * HH];   // aggregation buffer; reused for tanh output
__device__ float g_z[(size_t)NN * H2];
__device__ float g_assign[(size_t)NN * 2];
__device__ float g_sub[GG * HH];
__device__ float g_triv[GG * HH];
__device__ float g_gsum[GG * HH];
__device__ float g_cnt[GG];
__device__ float g_adj[GG * 4];
__device__ float g_pen[1];

// ---------------- utility: block reduce two floats ----------------
__device__ __forceinline__ float2 block_reduce2(float a, float b) {
    __shared__ float s0[8], s1[8];
    __shared__ float r0, r1;
    int wid = threadIdx.x >> 5, lane = threadIdx.x & 31;
#pragma unroll
    for (int o = 16; o > 0; o >>= 1) {
        a += __shfl_down_sync(0xffffffffu, a, o);
        b += __shfl_down_sync(0xffffffffu, b, o);
    }
    if (lane == 0) { s0[wid] = a; s1[wid] = b; }
    __syncthreads();
    if (wid == 0) {
        a = (lane < 8) ? s0[lane] : 0.f;
        b = (lane < 8) ? s1[lane] : 0.f;
#pragma unroll
        for (int o = 4; o > 0; o >>= 1) {
            a += __shfl_down_sync(0xffffffffu, a, o);
            b += __shfl_down_sync(0xffffffffu, b, o);
        }
        if (lane == 0) { r0 = a; r1 = b; }
    }
    __syncthreads();
    return make_float2(r0, r1);
}

// ---------------- kernels ----------------

__global__ __launch_bounds__(256) void zero_k() {
    int i = blockIdx.x * 256 + threadIdx.x;   // grid covers GG*HH
    if (i < GG * HH) { g_sub[i] = 0.f; g_triv[i] = 0.f; g_gsum[i] = 0.f; }
    if (i < GG)       g_cnt[i] = 0.f;
    if (i < GG * 4)   g_adj[i] = 0.f;
    if (i == 0)       g_pen[0] = 0.f;
}

// h[n][c] = sum_f atom_emb[f, x[n,f], c]
__global__ __launch_bounds__(256) void atom_enc(const int* __restrict__ x,
                                                const float* __restrict__ aemb) {
    int n = blockIdx.x;
    int c = threadIdx.x;
    __shared__ int xs[AFEA];
    if (threadIdx.x < AFEA) xs[threadIdx.x] = x[n * AFEA + threadIdx.x];
    __syncthreads();
    float s = 0.f;
#pragma unroll
    for (int f = 0; f < AFEA; f++)
        s += aemb[((size_t)f * AVOC + xs[f]) * HH + c];
    g_h[(size_t)n * HH + c] = s;
}

// agg = (1+eps[l]) * h
__global__ __launch_bounds__(256) void scale_copy(const float* __restrict__ eps, int l) {
    size_t i = (size_t)blockIdx.x * 256 + threadIdx.x;   // over NN*HH/4
    float sc = 1.f + eps[l];
    float4 v = reinterpret_cast<const float4*>(g_h)[i];
    v.x *= sc; v.y *= sc; v.z *= sc; v.w *= sc;
    reinterpret_cast<float4*>(g_agg)[i] = v;
}

// per-edge: agg[dst] += relu(h[src] + e_emb);  1 warp per edge, 8 channels/lane
__global__ __launch_bounds__(256) void edge_msg(const int* __restrict__ ei,
                                                const int* __restrict__ ea,
                                                const float* __restrict__ bemb) {
    int e = blockIdx.x * 8 + (threadIdx.x >> 5);
    if (e >= EE) return;
    int lane = threadIdx.x & 31;
    int src = ei[e], dst = ei[EE + e];
    int a0 = ea[e * 3 + 0], a1 = ea[e * 3 + 1], a2 = ea[e * 3 + 2];
    const float* b0 = bemb + (size_t)(0 * BVOC + a0) * HH;
    const float* b1 = bemb + (size_t)(1 * BVOC + a1) * HH;
    const float* b2 = bemb + (size_t)(2 * BVOC + a2) * HH;
    const float* hs = g_h + (size_t)src * HH;
    float* ag = g_agg + (size_t)dst * HH;
#pragma unroll
    for (int v = 0; v < 2; v++) {
        int c = v * 128 + lane * 4;
        float4 hv = *reinterpret_cast<const float4*>(hs + c);
        float4 e0 = *reinterpret_cast<const float4*>(b0 + c);
        float4 e1 = *reinterpret_cast<const float4*>(b1 + c);
        float4 e2 = *reinterpret_cast<const float4*>(b2 + c);
        float m0 = fmaxf(hv.x + e0.x + e1.x + e2.x, 0.f);
        float m1 = fmaxf(hv.y + e0.y + e1.y + e2.y, 0.f);
        float m2 = fmaxf(hv.z + e0.z + e1.z + e2.z, 0.f);
        float m3 = fmaxf(hv.w + e0.w + e1.w + e2.w, 0.f);
        atomicAdd(ag + c + 0, m0);
        atomicAdd(ag + c + 1, m1);
        atomicAdd(ag + c + 2, m2);
        atomicAdd(ag + c + 3, m3);
    }
}

// C[M,Nc] = A[M,K] @ B[K,Nc] with fused epilogue.
// mode 0: BN+ReLU (bias=b1, gamma, beta, mean, var); mode 1: +bias; mode 2: tanh(+bias)
__global__ __launch_bounds__(256) void gemm_k(const float* __restrict__ A,
                                              const float* __restrict__ B,
                                              float* __restrict__ C,
                                              int M, int K, int Nc, int mode,
                                              const float* __restrict__ bias,
                                              const float* __restrict__ gamma,
                                              const float* __restrict__ beta,
                                              const float* __restrict__ mean,
                                              const float* __restrict__ var) {
    __shared__ float As[16][65];
    __shared__ float Bs[16][64];
    const int tid = threadIdx.x;
    const int m0 = blockIdx.x * 64, n0 = blockIdx.y * 64;
    const int ty = tid >> 4, tx = tid & 15;
    const int ar = tid >> 2, ak = (tid & 3) << 2;
    const int bk = tid >> 4, bj = (tid & 15) << 2;
    const int lrow = m0 + ar;
    float acc[4][4] = {};
    for (int k0 = 0; k0 < K; k0 += 16) {
        float4 av = make_float4(0.f, 0.f, 0.f, 0.f);
        if (lrow < M) av = *reinterpret_cast<const float4*>(A + (size_t)lrow * K + k0 + ak);
        As[ak + 0][ar] = av.x; As[ak + 1][ar] = av.y;
        As[ak + 2][ar] = av.z; As[ak + 3][ar] = av.w;
        *reinterpret_cast<float4*>(&Bs[bk][bj]) =
            *reinterpret_cast<const float4*>(B + (size_t)(k0 + bk) * Nc + n0 + bj);
        __syncthreads();
#pragma unroll
        for (int k = 0; k < 16; k++) {
            float a0 = As[k][ty * 4 + 0];
            float a1 = As[k][ty * 4 + 1];
            float a2 = As[k][ty * 4 + 2];
            float a3 = As[k][ty * 4 + 3];
            float4 b = *reinterpret_cast<const float4*>(&Bs[k][tx * 4]);
            acc[0][0] += a0 * b.x; acc[0][1] += a0 * b.y; acc[0][2] += a0 * b.z; acc[0][3] += a0 * b.w;
            acc[1][0] += a1 * b.x; acc[1][1] += a1 * b.y; acc[1][2] += a1 * b.z; acc[1][3] += a1 * b.w;
            acc[2][0] += a2 * b.x; acc[2][1] += a2 * b.y; acc[2][2] += a2 * b.z; acc[2][3] += a2 * b.w;
            acc[3][0] += a3 * b.x; acc[3][1] += a3 * b.y; acc[3][2] += a3 * b.z; acc[3][3] += a3 * b.w;
        }
        __syncthreads();
    }
#pragma unroll
    for (int i = 0; i < 4; i++) {
        int r = m0 + ty * 4 + i;
        if (r >= M) continue;
#pragma unroll
        for (int j = 0; j < 4; j++) {
            int cix = n0 + tx * 4 + j;
            float v = acc[i][j];
            if (mode == 0) {
                float sc = gamma[cix] * rsqrtf(var[cix] + BN_EPS);
                v = (v + bias[cix] - mean[cix]) * sc + beta[cix];
                v = fmaxf(v, 0.f);
            } else if (mode == 1) {
                v += bias[cix];
            } else {
                v = tanhf(v + bias[cix]);
            }
            C[(size_t)r * Nc + cix] = v;
        }
    }
}

// per node: assignment softmax from tanh buffer (g_agg), pooling atomics, mask out
__global__ __launch_bounds__(256) void assign_pool(const float* __restrict__ c2W,
                                                   const float* __restrict__ c2b,
                                                   const int* __restrict__ batch,
                                                   float* __restrict__ out) {
    int n = blockIdx.x;
    int c = threadIdx.x;
    float t = g_agg[(size_t)n * HH + c];
    float2 lg = block_reduce2(t * c2W[c * 2 + 0], t * c2W[c * 2 + 1]);
    float l0 = lg.x + c2b[0], l1 = lg.y + c2b[1];
    float m = fmaxf(l0, l1);
    float e0 = expf(l0 - m), e1 = expf(l1 - m);
    float inv = 1.f / (e0 + e1);
    float a0 = e0 * inv, a1 = e1 * inv;
    float hv = g_h[(size_t)n * HH + c];
    int g = batch[n];
    atomicAdd(&g_sub[g * HH + c], a0 * hv);
    atomicAdd(&g_triv[g * HH + c], a1 * hv);
    atomicAdd(&g_gsum[g * HH + c], hv);
    if (c == 0) {
        atomicAdd(&g_cnt[g], 1.f);
        out[O_MASK + n] = (a0 > 0.5f) ? 1.f : 0.f;
        g_assign[(size_t)n * 2 + 0] = a0;
        g_assign[(size_t)n * 2 + 1] = a1;
    }
}

__global__ __launch_bounds__(256) void adj_k(const int* __restrict__ ei,
                                             const int* __restrict__ batch) {
    int e = blockIdx.x * 256 + threadIdx.x;
    if (e >= EE) return;
    int s = ei[e], d = ei[EE + e];
    int gs = batch[s], gd = batch[d];
    if (gs != gd) return;
    float as0 = g_assign[(size_t)s * 2], as1 = g_assign[(size_t)s * 2 + 1];
    float ad0 = g_assign[(size_t)d * 2], ad1 = g_assign[(size_t)d * 2 + 1];
    float* A = g_adj + gs * 4;
    atomicAdd(A + 0, as0 * ad0);
    atomicAdd(A + 1, as0 * ad1);
    atomicAdd(A + 2, as1 * ad0);
    atomicAdd(A + 3, as1 * ad1);
}

// write sub and graph_emb output regions
__global__ __launch_bounds__(256) void fin_pool(float* __restrict__ out) {
    int i = blockIdx.x * 256 + threadIdx.x;   // over GG*HH
    if (i >= GG * HH) return;
    int g = i / HH;
    out[O_SUB + i] = g_sub[i];
    out[O_GE + i] = g_gsum[i] / fmaxf(g_cnt[g], 1.f);
}

// head: log_softmax(relu(pool @ l1W + l1b) @ l2W + l2b); one block per graph.
// which=0 -> g_sub, which=1 -> g_triv
__global__ __launch_bounds__(256) void head_k(int which,
                                              const float* __restrict__ l1W,
                                              const float* __restrict__ l1b,
                                              const float* __restrict__ l2W,
                                              const float* __restrict__ l2b,
                                              float* __restrict__ out) {
    int g = blockIdx.x;
    int c = threadIdx.x;
    __shared__ float row[HH];
    row[c] = (which == 0) ? g_sub[(size_t)g * HH + c] : g_triv[(size_t)g * HH + c];
    __syncthreads();
    float acc = l1b[c];
#pragma unroll 4
    for (int k = 0; k < HH; k++)
        acc += row[k] * l1W[(size_t)k * HH + c];
    float z = fmaxf(acc, 0.f);
    float2 lg = block_reduce2(z * l2W[c * 2 + 0], z * l2W[c * 2 + 1]);
    if (c == 0) {
        float l0 = lg.x + l2b[0], l1 = lg.y + l2b[1];
        float m = fmaxf(l0, l1);
        float ls = logf(expf(l0 - m) + expf(l1 - m)) + m;
        out[g * 2 + 0] = l0 - ls;
        out[g * 2 + 1] = l1 - ls;
    }
}

__global__ __launch_bounds__(256) void pen_k() {
    int g = blockIdx.x * 256 + threadIdx.x;
    if (g >= GG) return;
    float a00 = g_adj[g * 4 + 0], a01 = g_adj[g * 4 + 1];
    float a10 = g_adj[g * 4 + 2], a11 = g_adj[g * 4 + 3];
    float r0 = fmaxf(fabsf(a00) + fabsf(a01), 1e-12f);
    float r1 = fmaxf(fabsf(a10) + fabsf(a11), 1e-12f);
    float d0 = a00 / r0 - 1.f, d1 = a11 / r1 - 1.f;
    atomicAdd(g_pen, d0 * d0 + d1 * d1);
}

__global__ void pen_w(float* __restrict__ out) {
    out[O_PEN] = g_pen[0] / (2.f * GG);
}

// ---------------- host launcher ----------------
extern "C" void kernel_launch(void* const* d_in, const int* in_sizes, int n_in,
                              void* d_out, int out_size) {
    int o = (n_in >= 24) ? 1 : 0;   // num_graphs scalar present at index 4?
    const int*   x     = (const int*)d_in[0];
    const int*   ei    = (const int*)d_in[1];
    const int*   ea    = (const int*)d_in[2];
    const int*   batch = (const int*)d_in[3];
    const float* aemb  = (const float*)d_in[4 + o];
    const float* bemb  = (const float*)d_in[5 + o];
    const float* eps   = (const float*)d_in[6 + o];
    const float* W1    = (const float*)d_in[7 + o];
    const float* b1    = (const float*)d_in[8 + o];
    const float* gma   = (const float*)d_in[9 + o];
    const float* bta   = (const float*)d_in[10 + o];
    const float* mu    = (const float*)d_in[11 + o];
    const float* var   = (const float*)d_in[12 + o];
    const float* W2    = (const float*)d_in[13 + o];
    const float* b2    = (const float*)d_in[14 + o];
    const float* c1W   = (const float*)d_in[15 + o];
    const float* c1b   = (const float*)d_in[16 + o];
    const float* c2W   = (const float*)d_in[17 + o];
    const float* c2b   = (const float*)d_in[18 + o];
    const float* l1W   = (const float*)d_in[19 + o];
    const float* l1b   = (const float*)d_in[20 + o];
    const float* l2W   = (const float*)d_in[21 + o];
    const float* l2b   = (const float*)d_in[22 + o];
    float* out = (float*)d_out;

    float *p_h, *p_agg, *p_z;
    cudaGetSymbolAddress((void**)&p_h, g_h);
    cudaGetSymbolAddress((void**)&p_agg, g_agg);
    cudaGetSymbolAddress((void**)&p_z, g_z);

    zero_k<<<(GG * HH + 255) / 256, 256>>>();
    atom_enc<<<NN, 256>>>(x, aemb);

    const int gmx = (NN + 63) / 64;
    for (int l = 0; l < LLAY; l++) {
        scale_copy<<<(NN * HH / 4 + 255) / 256, 256>>>(eps, l);
        edge_msg<<<(EE + 7) / 8, 256>>>(ei, ea, bemb + (size_t)l * BFEA * BVOC * HH);
        gemm_k<<<dim3(gmx, H2 / 64), 256>>>(p_agg, W1 + (size_t)l * HH * H2, p_z,
                                            NN, HH, H2, 0,
                                            b1 + (size_t)l * H2, gma + (size_t)l * H2,
                                            bta + (size_t)l * H2, mu + (size_t)l * H2,
                                            var + (size_t)l * H2);
        gemm_k<<<dim3(gmx, HH / 64), 256>>>(p_z, W2 + (size_t)l * H2 * HH, p_h,
                                            NN, H2, HH, 1,
                                            b2 + (size_t)l * HH, nullptr, nullptr,
                                            nullptr, nullptr);
    }

    // t = tanh(h @ c1W + c1b)  -> reuse g_agg
    gemm_k<<<dim3(gmx, HH / 64), 256>>>(p_h, c1W, p_agg, NN, HH, HH, 2,
                                        c1b, nullptr, nullptr, nullptr, nullptr);

    assign_pool<<<NN, 256>>>(c2W, c2b, batch, out);
    adj_k<<<(EE + 255) / 256, 256>>>(ei, batch);
    fin_pool<<<(GG * HH + 255) / 256, 256>>>(out);
    head_k<<<GG, 256>>>(0, l1W, l1b, l2W, l2b, out + O_HS);
    head_k<<<GG, 256>>>(1, l1W, l1b, l2W, l2b, out + O_HT);
    pen_k<<<(GG + 255) / 256, 256>>>();
    pen_w<<<1, 1>>>(out);
    (void)in_sizes; (void)out_size;
}

// round 2
// speedup vs baseline: 1.2886x; 1.2886x over previous
#include <cuda_runtime.h>
#include <math.h>

#define NN   100000
#define EE   400000
#define GG   2048
#define HH   256
#define H2   512
#define LLAY 5
#define AFEA 9
#define BFEA 3
#define AVOC 128
#define BVOC 16
#define BN_EPS 1e-5f

// Output layout (flattened float32), total 1,156,769 elements:
#define O_HS   0                      // head(sub)   [G,2]
#define O_HT   (2*GG)                 // head(triv)  [G,2]
#define O_SUB  (4*GG)                 // sub         [G,H]
#define O_GE   (4*GG + GG*HH)         // graph_emb   [G,H]
#define O_MASK (4*GG + 2*GG*HH)       // active_mask [N]
#define O_PEN  (4*GG + 2*GG*HH + NN)  // con_penalty scalar

// ---------------- scratch (device globals; no allocs allowed) ----------------
__device__ float g_h[(size_t)NN * HH];
__device__ float g_agg[(size_t)NN * HH];   // aggregation buffer; reused for tanh output
__device__ float g_z[(size_t)NN * H2];
__device__ float g_assign[(size_t)NN * 2];
__device__ float g_sub[GG * HH];
__device__ float g_triv[GG * HH];
__device__ float g_gsum[GG * HH];
__device__ float g_cnt[GG];
__device__ float g_adj[GG * 4];
__device__ float g_pen[1];

// ---------------- utility: block reduce two floats ----------------
__device__ __forceinline__ float2 block_reduce2(float a, float b) {
    __shared__ float s0[8], s1[8];
    __shared__ float r0, r1;
    int wid = threadIdx.x >> 5, lane = threadIdx.x & 31;
#pragma unroll
    for (int o = 16; o > 0; o >>= 1) {
        a += __shfl_down_sync(0xffffffffu, a, o);
        b += __shfl_down_sync(0xffffffffu, b, o);
    }
    if (lane == 0) { s0[wid] = a; s1[wid] = b; }
    __syncthreads();
    if (wid == 0) {
        a = (lane < 8) ? s0[lane] : 0.f;
        b = (lane < 8) ? s1[lane] : 0.f;
#pragma unroll
        for (int o = 4; o > 0; o >>= 1) {
            a += __shfl_down_sync(0xffffffffu, a, o);
            b += __shfl_down_sync(0xffffffffu, b, o);
        }
        if (lane == 0) { r0 = a; r1 = b; }
    }
    __syncthreads();
    return make_float2(r0, r1);
}

// ---------------- kernels ----------------

__global__ __launch_bounds__(256) void zero_k() {
    int i = blockIdx.x * 256 + threadIdx.x;   // grid covers GG*HH
    if (i < GG * HH) { g_sub[i] = 0.f; g_triv[i] = 0.f; g_gsum[i] = 0.f; }
    if (i < GG)       g_cnt[i] = 0.f;
    if (i < GG * 4)   g_adj[i] = 0.f;
    if (i == 0)       g_pen[0] = 0.f;
}

// h[n][c] = sum_f atom_emb[f, x[n,f], c];  also agg[n][c] = (1+eps[0])*h
__global__ __launch_bounds__(256) void atom_enc(const int* __restrict__ x,
                                                const float* __restrict__ aemb,
                                                const float* __restrict__ eps) {
    int n = blockIdx.x;
    int c = threadIdx.x;
    __shared__ int xs[AFEA];
    if (threadIdx.x < AFEA) xs[threadIdx.x] = x[n * AFEA + threadIdx.x];
    __syncthreads();
    float s = 0.f;
#pragma unroll
    for (int f = 0; f < AFEA; f++)
        s += aemb[((size_t)f * AVOC + xs[f]) * HH + c];
    g_h[(size_t)n * HH + c] = s;
    g_agg[(size_t)n * HH + c] = (1.f + eps[0]) * s;
}

// per-edge: agg[dst] += relu(h[src] + e_emb);  1 warp per edge, 8 channels/lane
__global__ __launch_bounds__(256) void edge_msg(const int* __restrict__ ei,
                                                const int* __restrict__ ea,
                                                const float* __restrict__ bemb) {
    int e = blockIdx.x * 8 + (threadIdx.x >> 5);
    if (e >= EE) return;
    int lane = threadIdx.x & 31;
    int src = ei[e], dst = ei[EE + e];
    int a0 = ea[e * 3 + 0], a1 = ea[e * 3 + 1], a2 = ea[e * 3 + 2];
    const float* b0 = bemb + (size_t)(0 * BVOC + a0) * HH;
    const float* b1 = bemb + (size_t)(1 * BVOC + a1) * HH;
    const float* b2 = bemb + (size_t)(2 * BVOC + a2) * HH;
    const float* hs = g_h + (size_t)src * HH;
    float* ag = g_agg + (size_t)dst * HH;
#pragma unroll
    for (int v = 0; v < 2; v++) {
        int c = v * 128 + lane * 4;
        float4 hv = *reinterpret_cast<const float4*>(hs + c);
        float4 e0 = *reinterpret_cast<const float4*>(b0 + c);
        float4 e1 = *reinterpret_cast<const float4*>(b1 + c);
        float4 e2 = *reinterpret_cast<const float4*>(b2 + c);
        float m0 = fmaxf(hv.x + e0.x + e1.x + e2.x, 0.f);
        float m1 = fmaxf(hv.y + e0.y + e1.y + e2.y, 0.f);
        float m2 = fmaxf(hv.z + e0.z + e1.z + e2.z, 0.f);
        float m3 = fmaxf(hv.w + e0.w + e1.w + e2.w, 0.f);
        atomicAdd(ag + c + 0, m0);
        atomicAdd(ag + c + 1, m1);
        atomicAdd(ag + c + 2, m2);
        atomicAdd(ag + c + 3, m3);
    }
}

// ---------------------------------------------------------------------------
// SGEMM: C[M,Nc] = A[M,K] @ B[K,Nc], 128x128 tile, 8x8 micro-tile, BK=8,
// double-buffered smem, float4 global/shared. Fused epilogues:
//   mode 0: BN + ReLU (bias=b1, gamma, beta, mean, var)
//   mode 1: +bias; optionally also write agg_out = (1+eps[next_l]) * value
//   mode 2: tanh(+bias)
// ---------------------------------------------------------------------------
__global__ __launch_bounds__(256, 2) void sgemm_k(
    const float* __restrict__ A, const float* __restrict__ B, float* __restrict__ C,
    int M, int K, int Nc, int mode,
    const float* __restrict__ bias,
    const float* __restrict__ gamma, const float* __restrict__ beta,
    const float* __restrict__ mean, const float* __restrict__ var,
    const float* __restrict__ eps, int next_l, float* __restrict__ agg_out) {
    __shared__ float As[2][8][136];   // transposed A tile, padded
    __shared__ float Bs[2][8][128];

    const int tid = threadIdx.x;
    const int m0 = blockIdx.x * 128, n0 = blockIdx.y * 128;
    // A load: thread -> (row, 4-col group)
    const int arow = tid >> 1;
    const int akc = (tid & 1) << 2;
    // B load: thread -> (k-row, 4-col group)
    const int brow = tid >> 5;
    const int bcol = (tid & 31) << 2;
    // compute mapping: split micro-tile (conflict-free LDS.128)
    const int tx = tid & 15, ty = tid >> 4;

    const int grow = m0 + arow;
    const float* Aptr = A + (size_t)grow * K + akc;
    const float* Bptr = B + (size_t)brow * Nc + n0 + bcol;

    float4 ap, bp;
    ap = (grow < M) ? *reinterpret_cast<const float4*>(Aptr)
                    : make_float4(0.f, 0.f, 0.f, 0.f);
    bp = *reinterpret_cast<const float4*>(Bptr);
    As[0][akc + 0][arow] = ap.x; As[0][akc + 1][arow] = ap.y;
    As[0][akc + 2][arow] = ap.z; As[0][akc + 3][arow] = ap.w;
    *reinterpret_cast<float4*>(&Bs[0][brow][bcol]) = bp;
    __syncthreads();

    float acc[8][8];
#pragma unroll
    for (int i = 0; i < 8; i++)
#pragma unroll
        for (int j = 0; j < 8; j++) acc[i][j] = 0.f;

    const int nk = K >> 3;
    int buf = 0;
    for (int kt = 0; kt < nk; kt++) {
        if (kt + 1 < nk) {
            int kb = (kt + 1) << 3;
            ap = (grow < M) ? *reinterpret_cast<const float4*>(Aptr + kb)
                            : make_float4(0.f, 0.f, 0.f, 0.f);
            bp = *reinterpret_cast<const float4*>(Bptr + (size_t)kb * Nc);
        }
#pragma unroll
        for (int k = 0; k < 8; k++) {
            float4 a0 = *reinterpret_cast<const float4*>(&As[buf][k][ty * 4]);
            float4 a1 = *reinterpret_cast<const float4*>(&As[buf][k][64 + ty * 4]);
            float4 b0 = *reinterpret_cast<const float4*>(&Bs[buf][k][tx * 4]);
            float4 b1 = *reinterpret_cast<const float4*>(&Bs[buf][k][64 + tx * 4]);
            float ar[8] = {a0.x, a0.y, a0.z, a0.w, a1.x, a1.y, a1.z, a1.w};
            float br[8] = {b0.x, b0.y, b0.z, b0.w, b1.x, b1.y, b1.z, b1.w};
#pragma unroll
            for (int i = 0; i < 8; i++)
#pragma unroll
                for (int j = 0; j < 8; j++)
                    acc[i][j] += ar[i] * br[j];
        }
        if (kt + 1 < nk) {
            int nb = buf ^ 1;
            As[nb][akc + 0][arow] = ap.x; As[nb][akc + 1][arow] = ap.y;
            As[nb][akc + 2][arow] = ap.z; As[nb][akc + 3][arow] = ap.w;
            *reinterpret_cast<float4*>(&Bs[nb][brow][bcol]) = bp;
        }
        __syncthreads();
        buf ^= 1;
    }

    // epilogue
    float aggsc = 0.f;
    if (agg_out) aggsc = 1.f + __ldg(eps + next_l);
#pragma unroll
    for (int i = 0; i < 8; i++) {
        int r = m0 + ((i < 4) ? (ty * 4 + i) : (64 + ty * 4 + i - 4));
        if (r >= M) continue;
#pragma unroll
        for (int jh = 0; jh < 2; jh++) {
            int cix = n0 + jh * 64 + tx * 4;
            float v[4];
#pragma unroll
            for (int j = 0; j < 4; j++) v[j] = acc[i][jh * 4 + j];
            if (mode == 0) {
#pragma unroll
                for (int j = 0; j < 4; j++) {
                    float sc = gamma[cix + j] * rsqrtf(var[cix + j] + BN_EPS);
                    float t = (v[j] + bias[cix + j] - mean[cix + j]) * sc + beta[cix + j];
                    v[j] = fmaxf(t, 0.f);
                }
            } else if (mode == 1) {
#pragma unroll
                for (int j = 0; j < 4; j++) v[j] += bias[cix + j];
            } else {
#pragma unroll
                for (int j = 0; j < 4; j++) v[j] = tanhf(v[j] + bias[cix + j]);
            }
            float4 o = make_float4(v[0], v[1], v[2], v[3]);
            *reinterpret_cast<float4*>(C + (size_t)r * Nc + cix) = o;
            if (agg_out) {
                float4 q = make_float4(v[0] * aggsc, v[1] * aggsc, v[2] * aggsc, v[3] * aggsc);
                *reinterpret_cast<float4*>(agg_out + (size_t)r * Nc + cix) = q;
            }
        }
    }
}

// per node: assignment softmax from tanh buffer (g_agg), pooling atomics, mask out
__global__ __launch_bounds__(256) void assign_pool(const float* __restrict__ c2W,
                                                   const float* __restrict__ c2b,
                                                   const int* __restrict__ batch,
                                                   float* __restrict__ out) {
    int n = blockIdx.x;
    int c = threadIdx.x;
    float t = g_agg[(size_t)n * HH + c];
    float2 lg = block_reduce2(t * c2W[c * 2 + 0], t * c2W[c * 2 + 1]);
    float l0 = lg.x + c2b[0], l1 = lg.y + c2b[1];
    float m = fmaxf(l0, l1);
    float e0 = expf(l0 - m), e1 = expf(l1 - m);
    float inv = 1.f / (e0 + e1);
    float a0 = e0 * inv, a1 = e1 * inv;
    float hv = g_h[(size_t)n * HH + c];
    int g = batch[n];
    atomicAdd(&g_sub[g * HH + c], a0 * hv);
    atomicAdd(&g_triv[g * HH + c], a1 * hv);
    atomicAdd(&g_gsum[g * HH + c], hv);
    if (c == 0) {
        atomicAdd(&g_cnt[g], 1.f);
        out[O_MASK + n] = (a0 > 0.5f) ? 1.f : 0.f;
        g_assign[(size_t)n * 2 + 0] = a0;
        g_assign[(size_t)n * 2 + 1] = a1;
    }
}

__global__ __launch_bounds__(256) void adj_k(const int* __restrict__ ei,
                                             const int* __restrict__ batch) {
    int e = blockIdx.x * 256 + threadIdx.x;
    if (e >= EE) return;
    int s = ei[e], d = ei[EE + e];
    int gs = batch[s], gd = batch[d];
    if (gs != gd) return;
    float as0 = g_assign[(size_t)s * 2], as1 = g_assign[(size_t)s * 2 + 1];
    float ad0 = g_assign[(size_t)d * 2], ad1 = g_assign[(size_t)d * 2 + 1];
    float* A = g_adj + gs * 4;
    atomicAdd(A + 0, as0 * ad0);
    atomicAdd(A + 1, as0 * ad1);
    atomicAdd(A + 2, as1 * ad0);
    atomicAdd(A + 3, as1 * ad1);
}

// write sub and graph_emb output regions
__global__ __launch_bounds__(256) void fin_pool(float* __restrict__ out) {
    int i = blockIdx.x * 256 + threadIdx.x;   // over GG*HH
    if (i >= GG * HH) return;
    int g = i / HH;
    out[O_SUB + i] = g_sub[i];
    out[O_GE + i] = g_gsum[i] / fmaxf(g_cnt[g], 1.f);
}

// head: log_softmax(relu(pool @ l1W + l1b) @ l2W + l2b); one block per graph.
// which=0 -> g_sub, which=1 -> g_triv
__global__ __launch_bounds__(256) void head_k(int which,
                                              const float* __restrict__ l1W,
                                              const float* __restrict__ l1b,
                                              const float* __restrict__ l2W,
                                              const float* __restrict__ l2b,
                                              float* __restrict__ out) {
    int g = blockIdx.x;
    int c = threadIdx.x;
    __shared__ float row[HH];
    row[c] = (which == 0) ? g_sub[(size_t)g * HH + c] : g_triv[(size_t)g * HH + c];
    __syncthreads();
    float acc = l1b[c];
#pragma unroll 4
    for (int k = 0; k < HH; k++)
        acc += row[k] * l1W[(size_t)k * HH + c];
    float z = fmaxf(acc, 0.f);
    float2 lg = block_reduce2(z * l2W[c * 2 + 0], z * l2W[c * 2 + 1]);
    if (c == 0) {
        float l0 = lg.x + l2b[0], l1 = lg.y + l2b[1];
        float m = fmaxf(l0, l1);
        float ls = logf(expf(l0 - m) + expf(l1 - m)) + m;
        out[g * 2 + 0] = l0 - ls;
        out[g * 2 + 1] = l1 - ls;
    }
}

__global__ __launch_bounds__(256) void pen_k() {
    int g = blockIdx.x * 256 + threadIdx.x;
    if (g >= GG) return;
    float a00 = g_adj[g * 4 + 0], a01 = g_adj[g * 4 + 1];
    float a10 = g_adj[g * 4 + 2], a11 = g_adj[g * 4 + 3];
    float r0 = fmaxf(fabsf(a00) + fabsf(a01), 1e-12f);
    float r1 = fmaxf(fabsf(a10) + fabsf(a11), 1e-12f);
    float d0 = a00 / r0 - 1.f, d1 = a11 / r1 - 1.f;
    atomicAdd(g_pen, d0 * d0 + d1 * d1);
}

__global__ void pen_w(float* __restrict__ out) {
    out[O_PEN] = g_pen[0] / (2.f * GG);
}

// ---------------- host launcher ----------------
extern "C" void kernel_launch(void* const* d_in, const int* in_sizes, int n_in,
                              void* d_out, int out_size) {
    int o = (n_in >= 24) ? 1 : 0;   // num_graphs scalar present at index 4?
    const int*   x     = (const int*)d_in[0];
    const int*   ei    = (const int*)d_in[1];
    const int*   ea    = (const int*)d_in[2];
    const int*   batch = (const int*)d_in[3];
    const float* aemb  = (const float*)d_in[4 + o];
    const float* bemb  = (const float*)d_in[5 + o];
    const float* eps   = (const float*)d_in[6 + o];
    const float* W1    = (const float*)d_in[7 + o];
    const float* b1    = (const float*)d_in[8 + o];
    const float* gma   = (const float*)d_in[9 + o];
    const float* bta   = (const float*)d_in[10 + o];
    const float* mu    = (const float*)d_in[11 + o];
    const float* var   = (const float*)d_in[12 + o];
    const float* W2    = (const float*)d_in[13 + o];
    const float* b2    = (const float*)d_in[14 + o];
    const float* c1W   = (const float*)d_in[15 + o];
    const float* c1b   = (const float*)d_in[16 + o];
    const float* c2W   = (const float*)d_in[17 + o];
    const float* c2b   = (const float*)d_in[18 + o];
    const float* l1W   = (const float*)d_in[19 + o];
    const float* l1b   = (const float*)d_in[20 + o];
    const float* l2W   = (const float*)d_in[21 + o];
    const float* l2b   = (const float*)d_in[22 + o];
    float* out = (float*)d_out;

    float *p_h, *p_agg, *p_z;
    cudaGetSymbolAddress((void**)&p_h, g_h);
    cudaGetSymbolAddress((void**)&p_agg, g_agg);
    cudaGetSymbolAddress((void**)&p_z, g_z);

    zero_k<<<(GG * HH + 255) / 256, 256>>>();
    atom_enc<<<NN, 256>>>(x, aemb, eps);

    const int gmx = (NN + 127) / 128;
    for (int l = 0; l < LLAY; l++) {
        edge_msg<<<(EE + 7) / 8, 256>>>(ei, ea, bemb + (size_t)l * BFEA * BVOC * HH);
        // z = relu(BN(agg @ W1[l] + b1[l]))    [N, 512]
        sgemm_k<<<dim3(gmx, H2 / 128), 256>>>(p_agg, W1 + (size_t)l * HH * H2, p_z,
                                              NN, HH, H2, 0,
                                              b1 + (size_t)l * H2, gma + (size_t)l * H2,
                                              bta + (size_t)l * H2, mu + (size_t)l * H2,
                                              var + (size_t)l * H2,
                                              nullptr, 0, nullptr);
        // h = z @ W2[l] + b2[l]                [N, 256]; fused agg init for next layer
        float* next_agg = (l + 1 < LLAY) ? p_agg : nullptr;
        sgemm_k<<<dim3(gmx, HH / 128), 256>>>(p_z, W2 + (size_t)l * H2 * HH, p_h,
                                              NN, H2, HH, 1,
                                              b2 + (size_t)l * HH, nullptr, nullptr,
                                              nullptr, nullptr,
                                              eps, l + 1, next_agg);
    }

    // t = tanh(h @ c1W + c1b)  -> reuse g_agg
    sgemm_k<<<dim3(gmx, HH / 128), 256>>>(p_h, c1W, p_agg, NN, HH, HH, 2,
                                          c1b, nullptr, nullptr, nullptr, nullptr,
                                          nullptr, 0, nullptr);

    assign_pool<<<NN, 256>>>(c2W, c2b, batch, out);
    adj_k<<<(EE + 255) / 256, 256>>>(ei, batch);
    fin_pool<<<(GG * HH + 255) / 256, 256>>>(out);
    head_k<<<GG, 256>>>(0, l1W, l1b, l2W, l2b, out + O_HS);
    head_k<<<GG, 256>>>(1, l1W, l1b, l2W, l2b, out + O_HT);
    pen_k<<<(GG + 255) / 256, 256>>>();
    pen_w<<<1, 1>>>(out);
    (void)in_sizes; (void)out_size;
}

// round 5
// speedup vs baseline: 1.3665x; 1.0605x over previous
#include <cuda_runtime.h>
#include <math.h>
#include <stdint.h>

#define NN   100000
#define EE   400000
#define GG   2048
#define HH   256
#define H2   512
#define LLAY 5
#define AFEA 9
#define BFEA 3
#define AVOC 128
#define BVOC 16
#define BN_EPS 1e-5f

// Output layout (flattened float32), total 1,156,769 elements:
#define O_HS   0                      // head(sub)   [G,2]
#define O_HT   (2*GG)                 // head(triv)  [G,2]
#define O_SUB  (4*GG)                 // sub         [G,H]
#define O_GE   (4*GG + GG*HH)         // graph_emb   [G,H]
#define O_MASK (4*GG + 2*GG*HH)       // active_mask [N]
#define O_PEN  (4*GG + 2*GG*HH + NN)  // con_penalty scalar

// ---------------- scratch (device globals; no allocs allowed) ----------------
__device__ float g_h[(size_t)NN * HH];
__device__ float g_agg[(size_t)NN * HH];   // aggregation buffer; reused for tanh output
__device__ float g_z[(size_t)NN * H2];
__device__ float g_assign[(size_t)NN * 2];
__device__ float g_sub[GG * HH];
__device__ float g_triv[GG * HH];
__device__ float g_gsum[GG * HH];
__device__ float g_cnt[GG];
__device__ float g_adj[GG * 4];
__device__ float g_pen[1];

// ---------------- utility ----------------
__device__ __forceinline__ float2 block_reduce2(float a, float b) {
    __shared__ float s0[8], s1[8];
    __shared__ float r0, r1;
    int wid = threadIdx.x >> 5, lane = threadIdx.x & 31;
#pragma unroll
    for (int o = 16; o > 0; o >>= 1) {
        a += __shfl_down_sync(0xffffffffu, a, o);
        b += __shfl_down_sync(0xffffffffu, b, o);
    }
    if (lane == 0) { s0[wid] = a; s1[wid] = b; }
    __syncthreads();
    if (wid == 0) {
        a = (lane < 8) ? s0[lane] : 0.f;
        b = (lane < 8) ? s1[lane] : 0.f;
#pragma unroll
        for (int o = 4; o > 0; o >>= 1) {
            a += __shfl_down_sync(0xffffffffu, a, o);
            b += __shfl_down_sync(0xffffffffu, b, o);
        }
        if (lane == 0) { r0 = a; r1 = b; }
    }
    __syncthreads();
    return make_float2(r0, r1);
}

__device__ __forceinline__ uint32_t f2tf32(float x) {
    uint32_t r;
    asm("cvt.rna.tf32.f32 %0, %1;" : "=r"(r) : "f"(x));
    return r;
}

__device__ __forceinline__ void mma_tf32(float* d, const uint32_t* a, uint32_t b0, uint32_t b1) {
    asm volatile("mma.sync.aligned.m16n8k8.row.col.f32.tf32.tf32.f32 "
                 "{%0,%1,%2,%3}, {%4,%5,%6,%7}, {%8,%9}, {%0,%1,%2,%3};"
                 : "+f"(d[0]), "+f"(d[1]), "+f"(d[2]), "+f"(d[3])
                 : "r"(a[0]), "r"(a[1]), "r"(a[2]), "r"(a[3]), "r"(b0), "r"(b1));
}

// ---------------- kernels ----------------

__global__ __launch_bounds__(256) void zero_k() {
    int i = blockIdx.x * 256 + threadIdx.x;
    if (i < GG * HH) { g_sub[i] = 0.f; g_triv[i] = 0.f; g_gsum[i] = 0.f; }
    if (i < GG)       g_cnt[i] = 0.f;
    if (i < GG * 4)   g_adj[i] = 0.f;
    if (i == 0)       g_pen[0] = 0.f;
}

// h[n][c] = sum_f atom_emb[f, x[n,f], c];  also agg[n][c] = (1+eps[0])*h
__global__ __launch_bounds__(256) void atom_enc(const int* __restrict__ x,
                                                const float* __restrict__ aemb,
                                                const float* __restrict__ eps) {
    int n = blockIdx.x;
    int c = threadIdx.x;
    __shared__ int xs[AFEA];
    if (threadIdx.x < AFEA) xs[threadIdx.x] = x[n * AFEA + threadIdx.x];
    __syncthreads();
    float s = 0.f;
#pragma unroll
    for (int f = 0; f < AFEA; f++)
        s += aemb[((size_t)f * AVOC + xs[f]) * HH + c];
    g_h[(size_t)n * HH + c] = s;
    g_agg[(size_t)n * HH + c] = (1.f + eps[0]) * s;
}

// per-edge: agg[dst] += relu(h[src] + e_emb)
__global__ __launch_bounds__(256) void edge_msg(const int* __restrict__ ei,
                                                const int* __restrict__ ea,
                                                const float* __restrict__ bemb) {
    int e = blockIdx.x * 8 + (threadIdx.x >> 5);
    if (e >= EE) return;
    int lane = threadIdx.x & 31;
    int src = ei[e], dst = ei[EE + e];
    int a0 = ea[e * 3 + 0], a1 = ea[e * 3 + 1], a2 = ea[e * 3 + 2];
    const float* b0 = bemb + (size_t)(0 * BVOC + a0) * HH;
    const float* b1 = bemb + (size_t)(1 * BVOC + a1) * HH;
    const float* b2 = bemb + (size_t)(2 * BVOC + a2) * HH;
    const float* hs = g_h + (size_t)src * HH;
    float* ag = g_agg + (size_t)dst * HH;
#pragma unroll
    for (int v = 0; v < 2; v++) {
        int c = v * 128 + lane * 4;
        float4 hv = *reinterpret_cast<const float4*>(hs + c);
        float4 e0 = *reinterpret_cast<const float4*>(b0 + c);
        float4 e1 = *reinterpret_cast<const float4*>(b1 + c);
        float4 e2 = *reinterpret_cast<const float4*>(b2 + c);
        float m0 = fmaxf(hv.x + e0.x + e1.x + e2.x, 0.f);
        float m1 = fmaxf(hv.y + e0.y + e1.y + e2.y, 0.f);
        float m2 = fmaxf(hv.z + e0.z + e1.z + e2.z, 0.f);
        float m3 = fmaxf(hv.w + e0.w + e1.w + e2.w, 0.f);
        atomicAdd(ag + c + 0, m0);
        atomicAdd(ag + c + 1, m1);
        atomicAdd(ag + c + 2, m2);
        atomicAdd(ag + c + 3, m3);
    }
}

// ---------------------------------------------------------------------------
// 3xTF32 tensor-core GEMM: C[M,Nc] = A[M,K] @ B[K,Nc], fp32-comparable accuracy.
// Block tile 128x128, BK=8, 256 threads = 8 warps, warp tile 32x64.
// A/B split into (hi, lo) tf32 at smem-store time; D += Ah*Bh + Ah*Bl + Al*Bh.
// Epilogues: mode 0: BN+ReLU; mode 1: +bias (+optional agg_out); mode 2: tanh(+bias)
// ---------------------------------------------------------------------------
#define ASTR 12
#define BSTR 136
__global__ __launch_bounds__(256) void mma_gemm(
    const float* __restrict__ A, const float* __restrict__ B, float* __restrict__ C,
    int M, int K, int Nc, int mode,
    const float* __restrict__ bias,
    const float* __restrict__ gamma, const float* __restrict__ beta,
    const float* __restrict__ mean, const float* __restrict__ var,
    const float* __restrict__ eps, int next_l, float* __restrict__ agg_out) {
    __shared__ uint32_t As_h[2][128 * ASTR];
    __shared__ uint32_t As_l[2][128 * ASTR];
    __shared__ uint32_t Bs_h[2][8 * BSTR];
    __shared__ uint32_t Bs_l[2][8 * BSTR];

    const int tid = threadIdx.x;
    const int m0 = blockIdx.x * 128, n0 = blockIdx.y * 128;
    const int lane = tid & 31, wid = tid >> 5;
    const int wm = (wid & 3) * 32;       // warp m offset in tile
    const int wn = (wid >> 2) * 64;      // warp n offset in tile
    const int g = lane >> 2, ct = lane & 3;

    // global staging mapping
    const int arow = tid >> 1, acol = (tid & 1) << 2;     // A: 128 x 8
    const int brow = tid >> 5, bcol = (tid & 31) << 2;    // B: 8 x 128
    const int grow = m0 + arow;
    const float* Aptr = A + (size_t)grow * K + acol;
    const float* Bptr = B + (size_t)brow * Nc + n0 + bcol;

    float4 ap, bp;
    ap = (grow < M) ? *reinterpret_cast<const float4*>(Aptr) : make_float4(0.f, 0.f, 0.f, 0.f);
    bp = *reinterpret_cast<const float4*>(Bptr);

    // split + store tile 0
    {
        float av[4] = {ap.x, ap.y, ap.z, ap.w};
        float bv[4] = {bp.x, bp.y, bp.z, bp.w};
#pragma unroll
        for (int j = 0; j < 4; j++) {
            uint32_t hi = f2tf32(av[j]);
            As_h[0][arow * ASTR + acol + j] = hi;
            As_l[0][arow * ASTR + acol + j] = f2tf32(av[j] - __uint_as_float(hi));
            uint32_t bh = f2tf32(bv[j]);
            Bs_h[0][brow * BSTR + bcol + j] = bh;
            Bs_l[0][brow * BSTR + bcol + j] = f2tf32(bv[j] - __uint_as_float(bh));
        }
    }
    __syncthreads();

    float acc[2][8][4];
#pragma unroll
    for (int mi = 0; mi < 2; mi++)
#pragma unroll
        for (int ni = 0; ni < 8; ni++)
#pragma unroll
            for (int q = 0; q < 4; q++) acc[mi][ni][q] = 0.f;

    const int nk = K >> 3;
    int buf = 0;
    for (int kt = 0; kt < nk; kt++) {
        if (kt + 1 < nk) {
            int kb = (kt + 1) << 3;
            ap = (grow < M) ? *reinterpret_cast<const float4*>(Aptr + kb)
                            : make_float4(0.f, 0.f, 0.f, 0.f);
            bp = *reinterpret_cast<const float4*>(Bptr + (size_t)kb * Nc);
        }
        // load A fragments (hi & lo)
        uint32_t ah[2][4], al[2][4];
#pragma unroll
        for (int mi = 0; mi < 2; mi++) {
            int mbase = wm + mi * 16;
#pragma unroll
            for (int q = 0; q < 4; q++) {
                int r = mbase + g + (q & 1) * 8;
                int c = ct + (q >> 1) * 4;
                ah[mi][q] = As_h[buf][r * ASTR + c];
                al[mi][q] = As_l[buf][r * ASTR + c];
            }
        }
#pragma unroll
        for (int ni = 0; ni < 8; ni++) {
            int nbase = wn + ni * 8 + g;
            uint32_t bh0 = Bs_h[buf][ct * BSTR + nbase];
            uint32_t bh1 = Bs_h[buf][(ct + 4) * BSTR + nbase];
            uint32_t bl0 = Bs_l[buf][ct * BSTR + nbase];
            uint32_t bl1 = Bs_l[buf][(ct + 4) * BSTR + nbase];
#pragma unroll
            for (int mi = 0; mi < 2; mi++) {
                mma_tf32(acc[mi][ni], ah[mi], bl0, bl1);   // Ah*Bl
                mma_tf32(acc[mi][ni], al[mi], bh0, bh1);   // Al*Bh
                mma_tf32(acc[mi][ni], ah[mi], bh0, bh1);   // Ah*Bh
            }
        }
        if (kt + 1 < nk) {
            int nb = buf ^ 1;
            float av[4] = {ap.x, ap.y, ap.z, ap.w};
            float bv[4] = {bp.x, bp.y, bp.z, bp.w};
#pragma unroll
            for (int j = 0; j < 4; j++) {
                uint32_t hi = f2tf32(av[j]);
                As_h[nb][arow * ASTR + acol + j] = hi;
                As_l[nb][arow * ASTR + acol + j] = f2tf32(av[j] - __uint_as_float(hi));
                uint32_t bh = f2tf32(bv[j]);
                Bs_h[nb][brow * BSTR + bcol + j] = bh;
                Bs_l[nb][brow * BSTR + bcol + j] = f2tf32(bv[j] - __uint_as_float(bh));
            }
        }
        __syncthreads();
        buf ^= 1;
    }

    // epilogue
    float aggsc = 0.f;
    if (agg_out) aggsc = 1.f + __ldg(eps + next_l);
#pragma unroll
    for (int mi = 0; mi < 2; mi++) {
#pragma unroll
        for (int half = 0; half < 2; half++) {
            int r = m0 + wm + mi * 16 + g + half * 8;
            if (r >= M) continue;
#pragma unroll
            for (int ni = 0; ni < 8; ni++) {
                int cix = n0 + wn + ni * 8 + ct * 2;
                float v0 = acc[mi][ni][half * 2 + 0];
                float v1 = acc[mi][ni][half * 2 + 1];
                if (mode == 0) {
                    float sc0 = gamma[cix + 0] * rsqrtf(var[cix + 0] + BN_EPS);
                    float sc1 = gamma[cix + 1] * rsqrtf(var[cix + 1] + BN_EPS);
                    v0 = fmaxf((v0 + bias[cix + 0] - mean[cix + 0]) * sc0 + beta[cix + 0], 0.f);
                    v1 = fmaxf((v1 + bias[cix + 1] - mean[cix + 1]) * sc1 + beta[cix + 1], 0.f);
                } else if (mode == 1) {
                    v0 += bias[cix + 0];
                    v1 += bias[cix + 1];
                } else {
                    v0 = tanhf(v0 + bias[cix + 0]);
                    v1 = tanhf(v1 + bias[cix + 1]);
                }
                *reinterpret_cast<float2*>(C + (size_t)r * Nc + cix) = make_float2(v0, v1);
                if (agg_out) {
                    *reinterpret_cast<float2*>(agg_out + (size_t)r * Nc + cix) =
                        make_float2(v0 * aggsc, v1 * aggsc);
                }
            }
        }
    }
}

// per node: assignment softmax from tanh buffer (g_agg), pooling atomics, mask out
__global__ __launch_bounds__(256) void assign_pool(const float* __restrict__ c2W,
                                                   const float* __restrict__ c2b,
                                                   const int* __restrict__ batch,
                                                   float* __restrict__ out) {
    int n = blockIdx.x;
    int c = threadIdx.x;
    float t = g_agg[(size_t)n * HH + c];
    float2 lg = block_reduce2(t * c2W[c * 2 + 0], t * c2W[c * 2 + 1]);
    float l0 = lg.x + c2b[0], l1 = lg.y + c2b[1];
    float m = fmaxf(l0, l1);
    float e0 = expf(l0 - m), e1 = expf(l1 - m);
    float inv = 1.f / (e0 + e1);
    float a0 = e0 * inv, a1 = e1 * inv;
    float hv = g_h[(size_t)n * HH + c];
    int g = batch[n];
    atomicAdd(&g_sub[g * HH + c], a0 * hv);
    atomicAdd(&g_triv[g * HH + c], a1 * hv);
    atomicAdd(&g_gsum[g * HH + c], hv);
    if (c == 0) {
        atomicAdd(&g_cnt[g], 1.f);
        out[O_MASK + n] = (a0 > 0.5f) ? 1.f : 0.f;
        g_assign[(size_t)n * 2 + 0] = a0;
        g_assign[(size_t)n * 2 + 1] = a1;
    }
}

__global__ __launch_bounds__(256) void adj_k(const int* __restrict__ ei,
                                             const int* __restrict__ batch) {
    int e = blockIdx.x * 256 + threadIdx.x;
    if (e >= EE) return;
    int s = ei[e], d = ei[EE + e];
    int gs = batch[s], gd = batch[d];
    if (gs != gd) return;
    float as0 = g_assign[(size_t)s * 2], as1 = g_assign[(size_t)s * 2 + 1];
    float ad0 = g_assign[(size_t)d * 2], ad1 = g_assign[(size_t)d * 2 + 1];
    float* A = g_adj + gs * 4;
    atomicAdd(A + 0, as0 * ad0);
    atomicAdd(A + 1, as0 * ad1);
    atomicAdd(A + 2, as1 * ad0);
    atomicAdd(A + 3, as1 * ad1);
}

// write sub and graph_emb output regions
__global__ __launch_bounds__(256) void fin_pool(float* __restrict__ out) {
    int i = blockIdx.x * 256 + threadIdx.x;
    if (i >= GG * HH) return;
    int g = i / HH;
    out[O_SUB + i] = g_sub[i];
    out[O_GE + i] = g_gsum[i] / fmaxf(g_cnt[g], 1.f);
}

// head: log_softmax(relu(pool @ l1W + l1b) @ l2W + l2b); one block per graph.
__global__ __launch_bounds__(256) void head_k(int which,
                                              const float* __restrict__ l1W,
                                              const float* __restrict__ l1b,
                                              const float* __restrict__ l2W,
                                              const float* __restrict__ l2b,
                                              float* __restrict__ out) {
    int g = blockIdx.x;
    int c = threadIdx.x;
    __shared__ float row[HH];
    row[c] = (which == 0) ? g_sub[(size_t)g * HH + c] : g_triv[(size_t)g * HH + c];
    __syncthreads();
    float acc = l1b[c];
#pragma unroll 4
    for (int k = 0; k < HH; k++)
        acc += row[k] * l1W[(size_t)k * HH + c];
    float z = fmaxf(acc, 0.f);
    float2 lg = block_reduce2(z * l2W[c * 2 + 0], z * l2W[c * 2 + 1]);
    if (c == 0) {
        float l0 = lg.x + l2b[0], l1 = lg.y + l2b[1];
        float m = fmaxf(l0, l1);
        float ls = logf(expf(l0 - m) + expf(l1 - m)) + m;
        out[g * 2 + 0] = l0 - ls;
        out[g * 2 + 1] = l1 - ls;
    }
}

__global__ __launch_bounds__(256) void pen_k() {
    int g = blockIdx.x * 256 + threadIdx.x;
    if (g >= GG) return;
    float a00 = g_adj[g * 4 + 0], a01 = g_adj[g * 4 + 1];
    float a10 = g_adj[g * 4 + 2], a11 = g_adj[g * 4 + 3];
    float r0 = fmaxf(fabsf(a00) + fabsf(a01), 1e-12f);
    float r1 = fmaxf(fabsf(a10) + fabsf(a11), 1e-12f);
    float d0 = a00 / r0 - 1.f, d1 = a11 / r1 - 1.f;
    atomicAdd(g_pen, d0 * d0 + d1 * d1);
}

__global__ void pen_w(float* __restrict__ out) {
    out[O_PEN] = g_pen[0] / (2.f * GG);
}

// ---------------- host launcher ----------------
extern "C" void kernel_launch(void* const* d_in, const int* in_sizes, int n_in,
                              void* d_out, int out_size) {
    int o = (n_in >= 24) ? 1 : 0;
    const int*   x     = (const int*)d_in[0];
    const int*   ei    = (const int*)d_in[1];
    const int*   ea    = (const int*)d_in[2];
    const int*   batch = (const int*)d_in[3];
    const float* aemb  = (const float*)d_in[4 + o];
    const float* bemb  = (const float*)d_in[5 + o];
    const float* eps   = (const float*)d_in[6 + o];
    const float* W1    = (const float*)d_in[7 + o];
    const float* b1    = (const float*)d_in[8 + o];
    const float* gma   = (const float*)d_in[9 + o];
    const float* bta   = (const float*)d_in[10 + o];
    const float* mu    = (const float*)d_in[11 + o];
    const float* var   = (const float*)d_in[12 + o];
    const float* W2    = (const float*)d_in[13 + o];
    const float* b2    = (const float*)d_in[14 + o];
    const float* c1W   = (const float*)d_in[15 + o];
    const float* c1b   = (const float*)d_in[16 + o];
    const float* c2W   = (const float*)d_in[17 + o];
    const float* c2b   = (const float*)d_in[18 + o];
    const float* l1W   = (const float*)d_in[19 + o];
    const float* l1b   = (const float*)d_in[20 + o];
    const float* l2W   = (const float*)d_in[21 + o];
    const float* l2b   = (const float*)d_in[22 + o];
    float* out = (float*)d_out;

    float *p_h, *p_agg, *p_z;
    cudaGetSymbolAddress((void**)&p_h, g_h);
    cudaGetSymbolAddress((void**)&p_agg, g_agg);
    cudaGetSymbolAddress((void**)&p_z, g_z);

    zero_k<<<(GG * HH + 255) / 256, 256>>>();
    atom_enc<<<NN, 256>>>(x, aemb, eps);

    const int gmx = (NN + 127) / 128;
    for (int l = 0; l < LLAY; l++) {
        edge_msg<<<(EE + 7) / 8, 256>>>(ei, ea, bemb + (size_t)l * BFEA * BVOC * HH);
        // z = relu(BN(agg @ W1[l] + b1[l]))    [N, 512]
        mma_gemm<<<dim3(gmx, H2 / 128), 256>>>(p_agg, W1 + (size_t)l * HH * H2, p_z,
                                               NN, HH, H2, 0,
                                               b1 + (size_t)l * H2, gma + (size_t)l * H2,
                                               bta + (size_t)l * H2, mu + (size_t)l * H2,
                                               var + (size_t)l * H2,
                                               nullptr, 0, nullptr);
        // h = z @ W2[l] + b2[l]                [N, 256]; fused agg init for next layer
        float* next_agg = (l + 1 < LLAY) ? p_agg : nullptr;
        mma_gemm<<<dim3(gmx, HH / 128), 256>>>(p_z, W2 + (size_t)l * H2 * HH, p_h,
                                               NN, H2, HH, 1,
                                               b2 + (size_t)l * HH, nullptr, nullptr,
                                               nullptr, nullptr,
                                               eps, l + 1, next_agg);
    }

    // t = tanh(h @ c1W + c1b)  -> reuse g_agg
    mma_gemm<<<dim3(gmx, HH / 128), 256>>>(p_h, c1W, p_agg, NN, HH, HH, 2,
                                           c1b, nullptr, nullptr, nullptr, nullptr,
                                           nullptr, 0, nullptr);

    assign_pool<<<NN, 256>>>(c2W, c2b, batch, out);
    adj_k<<<(EE + 255) / 256, 256>>>(ei, batch);
    fin_pool<<<(GG * HH + 255) / 256, 256>>>(out);
    head_k<<<GG, 256>>>(0, l1W, l1b, l2W, l2b, out + O_HS);
    head_k<<<GG, 256>>>(1, l1W, l1b, l2W, l2b, out + O_HT);
    pen_k<<<(GG + 255) / 256, 256>>>();
    pen_w<<<1, 1>>>(out);
    (void)in_sizes; (void)out_size;
}